// round 14
// baseline (speedup 1.0000x reference)
#include <cuda_runtime.h>
#include <math.h>
#include <stdint.h>

// Problem constants
#define BS     4
#define L_DIM  4800
#define S_DIM  4800
#define A_NUM  32
#define W0G    80
#define NROWS  (BS * L_DIM)
#define OUT_SIDE ((size_t)NROWS * 256)
#define KTOT   352                        // 256 feat + 96 geo

// Stats tiling
#define CCHUNK 19
#define CW     256
#define RCHUNK 16
#define RH     300

// MMA staging
#define PAD 36                            // padded row stride (floats)
#define STAGE_FLOATS (4 * 128 * PAD)      // Ab/As/Bb/Bs per stage = 18432
#define DYN_SMEM (2 * STAGE_FLOATS * 4)   // 147456 bytes (double buffered)

// ---------------- scratch (device globals; no allocation allowed) -----------
__device__ float d_anchors[2][BS][A_NUM][2];
__device__ float d_w2g[97][256];                    // row 96 = geo_b@Wg (epilogue bias)
__device__ float d_Btb[256 * KTOT];                 // B[n][k] tf32 high part
__device__ float d_Bts[256 * KTOT];                 // B[n][k] tf32 residual part
__device__ float d_Afb[2][NROWS][256];              // split feat, high part
__device__ float d_Afs[2][NROWS][256];              // split feat, residual part
__device__ float d_rowpart[BS][CCHUNK][L_DIM][4];
__device__ float d_colpart[BS][RCHUNK][S_DIM][4];

// ---------------- helpers ----------------------------------------------------
__device__ __forceinline__ uint32_t smem_u32(const void* p) {
    uint32_t a;
    asm("{ .reg .u64 t; cvta.to.shared.u64 t, %1; cvt.u32.u64 %0, t; }" : "=r"(a) : "l"(p));
    return a;
}
__device__ __forceinline__ float to_tf32(float x) {
    float y;
    asm("cvt.rna.tf32.f32 %0, %1;" : "=f"(y) : "f"(x));
    return y;
}
__device__ __forceinline__ uint32_t fbits(float x) { return __float_as_uint(x); }

__device__ __forceinline__ void cp16(uint32_t saddr, const float* g) {
    asm volatile("cp.async.cg.shared.global [%0], [%1], 16;" :: "r"(saddr), "l"(g));
}

// m16n8k8 tf32 mma (sm_80 baseline PTX)
__device__ __forceinline__ void mma8(float4& c,
                                     uint32_t a0, uint32_t a1, uint32_t a2, uint32_t a3,
                                     uint32_t b0, uint32_t b1) {
    asm volatile(
        "mma.sync.aligned.m16n8k8.row.col.f32.tf32.tf32.f32 "
        "{%0,%1,%2,%3},{%4,%5,%6,%7},{%8,%9},{%0,%1,%2,%3};"
        : "+f"(c.x), "+f"(c.y), "+f"(c.z), "+f"(c.w)
        : "r"(a0), "r"(a1), "r"(a2), "r"(a3), "r"(b0), "r"(b1));
}

// ---------------- tiny weight MLP -------------------------------------------
__device__ __forceinline__ float weight_mlp(float f0, float f1, float f2,
                                            const float* __restrict__ W1,
                                            const float* __restrict__ b1,
                                            const float* __restrict__ W2,
                                            const float* __restrict__ b2,
                                            const float* __restrict__ hW,
                                            const float* __restrict__ hb) {
    float h[3], r[3];
    #pragma unroll
    for (int j = 0; j < 3; ++j) {
        float x = f0 * W1[0 * 3 + j] + f1 * W1[1 * 3 + j] + f2 * W1[2 * 3 + j] + b1[j];
        h[j] = x > 0.f ? x : 0.01f * x;
    }
    #pragma unroll
    for (int j = 0; j < 3; ++j)
        r[j] = h[0] * W2[0 * 3 + j] + h[1] * W2[1 * 3 + j] + h[2] * W2[2 * 3 + j] + b2[j];
    float z = (f0 + r[0]) * hW[0] + (f1 + r[1]) * hW[1] + (f2 + r[2]) * hW[2] + hb[0];
    return tanhf(z);
}

// ---------------- prep1: w2g rows + geo part of Bt (split) -------------------
__global__ void prep1_kernel(const float* __restrict__ geo_W,
                             const float* __restrict__ geo_b,
                             const float* __restrict__ merge_W) {
    int j = blockIdx.x;        // 0..96 (96 = bias row)
    int n = threadIdx.x;       // 0..255
    float acc = 0.f;
    #pragma unroll 8
    for (int k = 0; k < 64; ++k) {
        float s = (j < 96) ? geo_W[j * 64 + k] : geo_b[k];
        acc += s * merge_W[(size_t)(256 + k) * 256 + n];
    }
    d_w2g[j][n] = acc;
    if (j < 96) {
        float vb = to_tf32(acc);
        d_Btb[(size_t)n * KTOT + 256 + j] = vb;
        d_Bts[(size_t)n * KTOT + 256 + j] = to_tf32(acc - vb);
    }
}

// ---------------- prep2: B transpose split + anchors + feat split ------------
__global__ void prep2_kernel(const float* __restrict__ merge_W,
                             const float* __restrict__ mconf,
                             const int* __restrict__ i_ids,
                             const int* __restrict__ j_ids,
                             const float* __restrict__ feat0,
                             const float* __restrict__ feat1) {
    __shared__ float sv[512];
    int bx = blockIdx.x;
    int tid = threadIdx.x;
    if (bx < 256) {
        int n = bx, k = tid;
        float x = merge_W[(size_t)k * 256 + n];
        float vb = to_tf32(x);
        d_Btb[(size_t)n * KTOT + k] = vb;
        d_Bts[(size_t)n * KTOT + k] = to_tf32(x - vb);
    } else if (bx < 260) {
        int b = bx - 256;
        sv[tid]       = mconf[b * 512 + tid];
        sv[tid + 256] = mconf[b * 512 + tid + 256];
        __syncthreads();
        #pragma unroll
        for (int h = 0; h < 2; ++h) {
            int c = tid + h * 256;
            float v = sv[c];
            int rank = 0;
            #pragma unroll 8
            for (int k = 0; k < 512; ++k) {
                float u = sv[k];
                rank += (u > v) || (u == v && k < c);
            }
            if (rank < A_NUM) {
                int i = i_ids[b * 512 + c];
                int jj = j_ids[b * 512 + c];
                d_anchors[0][b][rank][0] = (float)(i / W0G);
                d_anchors[0][b][rank][1] = (float)(i % W0G);
                d_anchors[1][b][rank][0] = (float)(jj / W0G);
                d_anchors[1][b][rank][1] = (float)(jj % W0G);
            }
        }
    } else {
        // feat split: 300 blocks, each covers 128 rows of one side
        int bb = bx - 260;                 // 0..299
        int side = bb / 150;
        int r0 = (bb % 150) * 128;
        const float* f = side ? feat1 : feat0;
        #pragma unroll 4
        for (int i = 0; i < 32; ++i) {
            int off = i * 1024 + tid * 4;  // 0..32767 (128 rows x 256 cols)
            int row = off >> 8, k = off & 255;
            float4 v = __ldg((const float4*)(f + (size_t)(r0 + row) * 256 + k));
            float4 vb, vs;
            vb.x = to_tf32(v.x); vs.x = to_tf32(v.x - vb.x);
            vb.y = to_tf32(v.y); vs.y = to_tf32(v.y - vb.y);
            vb.z = to_tf32(v.z); vs.z = to_tf32(v.z - vb.z);
            vb.w = to_tf32(v.w); vs.w = to_tf32(v.w - vb.w);
            *(float4*)&d_Afb[side][r0 + row][k] = vb;
            *(float4*)&d_Afs[side][r0 + row][k] = vs;
        }
    }
}

// ---------------- stats: single-pass fused (measured 89us) -------------------
__global__ __launch_bounds__(256) void stats_kernel(const float* __restrict__ cm) {
    const int b = blockIdx.z, ry = blockIdx.y, cx = blockIdx.x;
    const int l0 = ry * RH, c0 = cx * CW;
    const int lane = threadIdx.x & 31, w = threadIdx.x >> 5;
    const float* base = cm + (size_t)b * L_DIM * S_DIM + (size_t)l0 * S_DIM + c0;
    const bool v1 = (c0 + 128 + lane * 4) < S_DIM;

    float ca[2][4][4];
    #pragma unroll
    for (int i = 0; i < 2; ++i)
        #pragma unroll
        for (int q = 0; q < 4; ++q) {
            ca[i][q][0] = -1e30f; ca[i][q][1] = 0.f; ca[i][q][2] = 0.f; ca[i][q][3] = 0.f;
        }

    #pragma unroll 2
    for (int l = w; l < RH; l += 8) {
        const float* rowp = base + (size_t)l * S_DIM;
        float4 x0 = __ldg((const float4*)rowp + lane);
        float4 x1;
        if (v1) x1 = __ldg((const float4*)rowp + 32 + lane);
        float mx = -1e30f, s = 0.f, sq = 0.f, se = 0.f;
        {
            float vv[4] = {x0.x, x0.y, x0.z, x0.w};
            #pragma unroll
            for (int q = 0; q < 4; ++q) {
                float v = vv[q];
                float cc = fmaxf(v, 1e-5f);
                float e = cc * __logf(cc);
                mx = fmaxf(mx, v); s += v; sq += v * v; se += e;
                ca[0][q][0] = fmaxf(ca[0][q][0], v); ca[0][q][1] += v;
                ca[0][q][2] += v * v;                ca[0][q][3] += e;
            }
        }
        if (v1) {
            float vv[4] = {x1.x, x1.y, x1.z, x1.w};
            #pragma unroll
            for (int q = 0; q < 4; ++q) {
                float v = vv[q];
                float cc = fmaxf(v, 1e-5f);
                float e = cc * __logf(cc);
                mx = fmaxf(mx, v); s += v; sq += v * v; se += e;
                ca[1][q][0] = fmaxf(ca[1][q][0], v); ca[1][q][1] += v;
                ca[1][q][2] += v * v;                ca[1][q][3] += e;
            }
        }
        #pragma unroll
        for (int o = 16; o; o >>= 1) {
            mx = fmaxf(mx, __shfl_xor_sync(0xffffffffu, mx, o));
            s  += __shfl_xor_sync(0xffffffffu, s, o);
            sq += __shfl_xor_sync(0xffffffffu, sq, o);
            se += __shfl_xor_sync(0xffffffffu, se, o);
        }
        if (lane == 0)
            *(float4*)&d_rowpart[b][cx][l0 + l][0] = make_float4(mx, s, sq, se);
    }

    __shared__ float sm[8][4][CW];
    #pragma unroll
    for (int i = 0; i < 2; ++i)
        #pragma unroll
        for (int q = 0; q < 4; ++q) {
            int c = i * 128 + lane * 4 + q;
            sm[w][0][c] = ca[i][q][0]; sm[w][1][c] = ca[i][q][1];
            sm[w][2][c] = ca[i][q][2]; sm[w][3][c] = ca[i][q][3];
        }
    __syncthreads();
    int j = threadIdx.x;
    if (c0 + j < S_DIM) {
        float M = -1e30f, S = 0.f, Q = 0.f, E = 0.f;
        #pragma unroll
        for (int ww = 0; ww < 8; ++ww) {
            M = fmaxf(M, sm[ww][0][j]); S += sm[ww][1][j];
            Q += sm[ww][2][j]; E += sm[ww][3][j];
        }
        *(float4*)&d_colpart[b][ry][c0 + j][0] = make_float4(M, S, Q, E);
    }
}

// ---------------- merge MMA: cp.async double-buffered 3xTF32 -----------------
// D = [feat | w*G] @ Bt^T via Ab*Bb + As*Bb + Ab*Bs. 128x128 tile, 8 warps.
__global__ __launch_bounds__(256) void merge_mma_kernel(
        const float* __restrict__ merge_b,
        const float* __restrict__ W1, const float* __restrict__ b1,
        const float* __restrict__ W2, const float* __restrict__ b2,
        const float* __restrict__ hW, const float* __restrict__ hb,
        float* __restrict__ out) {
    extern __shared__ float smf[];
    __shared__ float sW[128];

    const int tid = threadIdx.x, wid = tid >> 5, lane = tid & 31;
    const int side = blockIdx.y;
    const int row0 = blockIdx.x * 128;
    const int col0 = blockIdx.z * 128;
    const uint32_t smbase = smem_u32(smf);

    // per-row weights (finalize folded in)
    if (tid < 128) {
        int row = row0 + tid;
        int b = row / L_DIM, p = row % L_DIM;
        float M = -1e30f, S = 0.f, Q = 0.f, E = 0.f;
        if (side == 0) {
            #pragma unroll
            for (int r = 0; r < CCHUNK; ++r) {
                float4 q4 = *(const float4*)&d_rowpart[b][r][p][0];
                M = fmaxf(M, q4.x); S += q4.y; Q += q4.z; E += q4.w;
            }
        } else {
            #pragma unroll
            for (int r = 0; r < RCHUNK; ++r) {
                float4 q4 = *(const float4*)&d_colpart[b][r][p][0];
                M = fmaxf(M, q4.x); S += q4.y; Q += q4.z; E += q4.w;
            }
        }
        const float inv_n = 1.f / 4800.f;
        float var = (Q - S * S * inv_n) * (1.f / 4799.f);
        float stdv = sqrtf(fmaxf(var, 0.f));
        float ent = -E * inv_n;
        sW[tid] = weight_mlp(M, stdv, ent, W1, b1, W2, b2, hW, hb);
    }
    __syncthreads();

    const int wm = (wid & 3) * 32;
    const int wn = (wid >> 2) * 64;
    const int r = lane >> 2, cg = lane & 3;
    float4 acc[2][8];
    #pragma unroll
    for (int mt = 0; mt < 2; ++mt)
        #pragma unroll
        for (int nt = 0; nt < 8; ++nt)
            acc[mt][nt] = make_float4(0.f, 0.f, 0.f, 0.f);

    // stage layout (floats): Ab @0, As @4608, Bb @9216, Bs @13824
    const float* Afb = &d_Afb[side][0][0];
    const float* Afs = &d_Afs[side][0][0];

    // issue cp.async copies for one chunk
    auto issue = [&](int ct) {
        int s = ct & 1;
        uint32_t st = smbase + (uint32_t)s * STAGE_FLOATS * 4;
        if (ct < 8) {
            #pragma unroll
            for (int q = 0; q < 4; ++q) {
                int idx = tid * 4 + q;             // 0..1023
                int row = idx >> 3, qi = idx & 7;
                size_t g = (size_t)(row0 + row) * 256 + ct * 32 + qi * 4;
                uint32_t so = (uint32_t)(row * PAD + qi * 4) * 4;
                cp16(st + so, Afb + g);
                cp16(st + 4608 * 4 + so, Afs + g);
            }
        }
        #pragma unroll
        for (int q = 0; q < 4; ++q) {
            int idx = tid * 4 + q;
            int row = idx >> 3, qi = idx & 7;
            size_t g = (size_t)(col0 + row) * KTOT + ct * 32 + qi * 4;
            uint32_t so = (uint32_t)(row * PAD + qi * 4) * 4;
            cp16(st + 9216 * 4 + so, d_Btb + g);
            cp16(st + 13824 * 4 + so, d_Bts + g);
        }
        asm volatile("cp.async.commit_group;" ::: "memory");
    };

    issue(0);
    const int m = tid >> 1, half = tid & 1;
    for (int ct = 0; ct < 11; ++ct) {
        if (ct < 10) {
            issue(ct + 1);
            asm volatile("cp.async.wait_group 1;" ::: "memory");
        } else {
            asm volatile("cp.async.wait_group 0;" ::: "memory");
        }
        __syncthreads();

        float* stage = smf + (ct & 1) * STAGE_FLOATS;
        float* sAb = stage;
        float* sAs = stage + 4608;
        float* sBb = stage + 9216;
        float* sBs = stage + 13824;

        if (ct >= 8) {
            // manual geo A staging (A-part of this stage untouched by cp.async)
            int row = row0 + m;
            int bb = row / L_DIM, p = row % L_DIM;
            float px = (float)(p / W0G), py = (float)(p % W0G);
            float wv = sW[m];
            #pragma unroll
            for (int i = 0; i < 16; ++i) {
                int kk = half * 16 + i;
                int aidx = (ct - 8) * 32 + kk;
                int a = aidx / 3, comp = aidx - 3 * a;
                float dx = px - d_anchors[side][bb][a][0];
                float dy = py - d_anchors[side][bb][a][1];
                float val;
                if (comp == 0)      val = fminf(fmaxf(dx, -100.f), 100.f);
                else if (comp == 1) val = fminf(fmaxf(dy, -100.f), 100.f);
                else                val = fminf(sqrtf(dx * dx + dy * dy), 100.f);
                val = val * 0.01f * wv;
                float vb = to_tf32(val);
                sAb[m * PAD + kk] = vb;
                sAs[m * PAD + kk] = to_tf32(val - vb);
            }
            __syncthreads();
        }

        // ---- compute: 4 k-steps of 8 ---------------------------------------
        #pragma unroll
        for (int ks = 0; ks < 4; ++ks) {
            int k0 = ks * 8;
            uint32_t ab[2][4], av[2][4];
            #pragma unroll
            for (int mt = 0; mt < 2; ++mt) {
                int rb = wm + mt * 16;
                ab[mt][0] = fbits(sAb[(rb + r) * PAD + k0 + cg]);
                ab[mt][1] = fbits(sAb[(rb + r + 8) * PAD + k0 + cg]);
                ab[mt][2] = fbits(sAb[(rb + r) * PAD + k0 + cg + 4]);
                ab[mt][3] = fbits(sAb[(rb + r + 8) * PAD + k0 + cg + 4]);
                av[mt][0] = fbits(sAs[(rb + r) * PAD + k0 + cg]);
                av[mt][1] = fbits(sAs[(rb + r + 8) * PAD + k0 + cg]);
                av[mt][2] = fbits(sAs[(rb + r) * PAD + k0 + cg + 4]);
                av[mt][3] = fbits(sAs[(rb + r + 8) * PAD + k0 + cg + 4]);
            }
            #pragma unroll
            for (int nt = 0; nt < 8; ++nt) {
                int n = wn + nt * 8 + r;
                uint32_t bb0 = fbits(sBb[n * PAD + k0 + cg]);
                uint32_t bb1 = fbits(sBb[n * PAD + k0 + cg + 4]);
                uint32_t bs0 = fbits(sBs[n * PAD + k0 + cg]);
                uint32_t bs1 = fbits(sBs[n * PAD + k0 + cg + 4]);
                mma8(acc[0][nt], ab[0][0], ab[0][1], ab[0][2], ab[0][3], bb0, bb1);
                mma8(acc[1][nt], ab[1][0], ab[1][1], ab[1][2], ab[1][3], bb0, bb1);
                mma8(acc[0][nt], av[0][0], av[0][1], av[0][2], av[0][3], bb0, bb1);
                mma8(acc[1][nt], av[1][0], av[1][1], av[1][2], av[1][3], bb0, bb1);
                mma8(acc[0][nt], ab[0][0], ab[0][1], ab[0][2], ab[0][3], bs0, bs1);
                mma8(acc[1][nt], ab[1][0], ab[1][1], ab[1][2], ab[1][3], bs0, bs1);
            }
        }
        __syncthreads();
    }

    // ---- epilogue: out = acc + merge_b + w * bg ----------------------------
    #pragma unroll
    for (int mt = 0; mt < 2; ++mt) {
        int rl = wm + mt * 16 + r;
        float wv0 = sW[rl], wv1 = sW[rl + 8];
        float* o0 = out + (size_t)side * OUT_SIDE + (size_t)(row0 + rl) * 256;
        float* o1 = out + (size_t)side * OUT_SIDE + (size_t)(row0 + rl + 8) * 256;
        #pragma unroll
        for (int nt = 0; nt < 8; ++nt) {
            int c = col0 + wn + nt * 8 + 2 * cg;
            float mb0 = __ldg(&merge_b[c]), mb1 = __ldg(&merge_b[c + 1]);
            float bg0 = d_w2g[96][c], bg1 = d_w2g[96][c + 1];
            float2 v0, v1;
            v0.x = acc[mt][nt].x + mb0 + wv0 * bg0;
            v0.y = acc[mt][nt].y + mb1 + wv0 * bg1;
            v1.x = acc[mt][nt].z + mb0 + wv1 * bg0;
            v1.y = acc[mt][nt].w + mb1 + wv1 * bg1;
            *(float2*)(o0 + c) = v0;
            *(float2*)(o1 + c) = v1;
        }
    }
}

// ---------------- launch -----------------------------------------------------
extern "C" void kernel_launch(void* const* d_in, const int* in_sizes, int n_in,
                              void* d_out, int out_size) {
    const float* feat0   = (const float*)d_in[0];
    const float* feat1   = (const float*)d_in[1];
    const float* cm      = (const float*)d_in[2];
    const float* mconf   = (const float*)d_in[3];
    const int*   i_ids   = (const int*)d_in[4];
    const int*   j_ids   = (const int*)d_in[5];
    const float* geo_W   = (const float*)d_in[6];
    const float* geo_b   = (const float*)d_in[7];
    const float* res_W1  = (const float*)d_in[8];
    const float* res_b1  = (const float*)d_in[9];
    const float* res_W2  = (const float*)d_in[10];
    const float* res_b2  = (const float*)d_in[11];
    const float* head_W  = (const float*)d_in[12];
    const float* head_b  = (const float*)d_in[13];
    const float* merge_W = (const float*)d_in[14];
    const float* merge_b = (const float*)d_in[15];
    float* out = (float*)d_out;

    cudaFuncSetAttribute(merge_mma_kernel,
                         cudaFuncAttributeMaxDynamicSharedMemorySize, DYN_SMEM);

    prep1_kernel<<<97, 256>>>(geo_W, geo_b, merge_W);                    // idx 0
    prep2_kernel<<<560, 256>>>(merge_W, mconf, i_ids, j_ids, feat0, feat1); // idx 1
    stats_kernel<<<dim3(CCHUNK, RCHUNK, BS), 256>>>(cm);                 // idx 2
    merge_mma_kernel<<<dim3(150, 2, 2), 256, DYN_SMEM>>>(                // idx 3 (profiled)
        merge_b, res_W1, res_b1, res_W2, res_b2, head_W, head_b, out);
}